// round 6
// baseline (speedup 1.0000x reference)
#include <cuda_runtime.h>
#include <math.h>

#define NT 256
#define FR_STRIDE 100         // floats per thread frame region (400B: 16B-aligned, conflict-friendly)
#define DF_STRIDE 97          // odd -> conflict-free scalar LDS across aa
#define AT_STRIDE 51          // odd
#define FR_FLOATS (FR_STRIDE * NT)
#define DF_FLOATS (21 * DF_STRIDE)
#define AT_FLOATS (21 * AT_STRIDE)
#define SMEM_FLOATS (FR_FLOATS + DF_FLOATS + AT_FLOATS)   // 28708 floats = 114832 B -> 2 blocks/SM

struct V3 { float x, y, z; };

__device__ __forceinline__ V3 vsub(V3 a, V3 b) { return V3{a.x - b.x, a.y - b.y, a.z - b.z}; }
__device__ __forceinline__ V3 vcross(V3 a, V3 b) {
    return V3{a.y * b.z - a.z * b.y, a.z * b.x - a.x * b.z, a.x * b.y - a.y * b.x};
}
__device__ __forceinline__ float vdot(V3 a, V3 b) { return a.x * b.x + a.y * b.y + a.z * b.z; }

// fast atan2: minimax poly on [0,1], quadrant fixes. |err| ~1e-6 rad, far under 1e-3 budget.
// (0,0) -> NaN -> caught by caller's nan_to_num (reference arctan2(0,0)=0, same result).
__device__ __forceinline__ float fast_atan2f(float y, float x) {
    float ax = fabsf(x), ay = fabsf(y);
    float mx = fmaxf(ax, ay), mn = fminf(ax, ay);
    float t = __fdividef(mn, mx);
    float t2 = t * t;
    float p = -0.0117212f;
    p = fmaf(p, t2,  0.05265332f);
    p = fmaf(p, t2, -0.11643287f);
    p = fmaf(p, t2,  0.19354346f);
    p = fmaf(p, t2, -0.33262347f);
    p = fmaf(p, t2,  0.99997726f);
    float r = p * t;
    r = (ay > ax) ? (1.5707963267948966f - r) : r;
    r = (x < 0.0f) ? (3.14159265358979323846f - r) : r;
    return copysignf(r, y);
}

// Matches reference _dihedral (including nan_to_num -> 0)
__device__ __forceinline__ float dihedral(V3 p0, V3 p1, V3 p2, V3 p3) {
    V3 b0 = vsub(p0, p1);
    V3 b1 = vsub(p2, p1);
    V3 b2 = vsub(p3, p2);
    V3 v1 = vcross(b0, b1);
    V3 v2 = vcross(b2, b1);
    float y = vdot(vcross(v1, v2), b1) * rsqrtf(vdot(b1, b1));
    float x = vdot(v1, v2);
    float a = fast_atan2f(y, x);
    return (a != a) ? 0.0f : a;
}

__global__ void __launch_bounds__(NT)
idealizer_kernel(const int* __restrict__ aa,
                 const float* __restrict__ bb,      // [n,4,3]
                 const float* __restrict__ tor,     // [n,4]
                 const float* __restrict__ dfr,     // [21,8,4,4]
                 const int* __restrict__ gidx,      // [21,14]
                 const float* __restrict__ amask,   // [21,14]
                 const float* __restrict__ lit,     // [21,14,3]
                 float* __restrict__ out,           // [n,14,3]
                 int n)
{
    extern __shared__ float smem[];
    float* fr_s = smem;                 // per-thread frame region [tid*100 .. +96); doubles as bb stage, then output stage
    float* df_s = smem + FR_FLOATS;     // [21][97]
    float* at_s = df_s + DF_FLOATS;     // [21][51]

    const int tid = threadIdx.x;
    const int base = blockIdx.x * NT;
    const int i = base + tid;
    const bool active = i < n;

    float* myfr = fr_s + tid * FR_STRIDE;

    float bbv[12];
    float t4x, t4y, t4z, t4w;
    int a_i = 0;

    if (active) {
        const float4* b4 = reinterpret_cast<const float4*>(bb) + (size_t)i * 3;
        float4 q0 = b4[0], q1 = b4[1], q2 = b4[2];
        bbv[0] = q0.x; bbv[1] = q0.y; bbv[2]  = q0.z; bbv[3]  = q0.w;
        bbv[4] = q1.x; bbv[5] = q1.y; bbv[6]  = q1.z; bbv[7]  = q1.w;
        bbv[8] = q2.x; bbv[9] = q2.y; bbv[10] = q2.z; bbv[11] = q2.w;
        const float4 t4 = reinterpret_cast<const float4*>(tor)[i];
        t4x = t4.x; t4y = t4.y; t4z = t4.z; t4w = t4.w;
        a_i = aa[i];
        // stage bb for neighbor dihedral reads (vectorized, own region)
        float4* st = reinterpret_cast<float4*>(myfr);
        st[0] = q0; st[1] = q1; st[2] = q2;
    }

    // ---- cooperative table loads into padded smem ----
    for (int idx = tid; idx < 21 * 96; idx += NT) {
        int a = idx / 96;
        int r = idx - a * 96;                   // r = k*12 + j
        int k = r / 12;
        int j = r - k * 12;
        df_s[a * DF_STRIDE + r] = __ldg(dfr + a * 128 + k * 16 + j);
    }
    for (int idx = tid; idx < 21 * 10; idx += NT) {
        int a = idx / 10;
        int at = idx - a * 10;
        int ai = a * 14 + at + 4;
        float* dst = at_s + a * AT_STRIDE + at * 5;
        dst[0] = __int_as_float(__ldg(gidx + ai));
        dst[1] = __ldg(amask + ai);
        dst[2] = __ldg(lit + (size_t)ai * 3 + 0);
        dst[3] = __ldg(lit + (size_t)ai * 3 + 1);
        dst[4] = __ldg(lit + (size_t)ai * 3 + 2);
    }
    __syncthreads();

    float ang[7];
    float M00, M01, M02, M10, M11, M12, M20, M21, M22;
    V3 CAv;

    if (active) {
        V3 Nv  = {bbv[0], bbv[1], bbv[2]};
        CAv    = {bbv[3], bbv[4], bbv[5]};
        V3 Cv  = {bbv[6], bbv[7], bbv[8]};

        // ---- dihedrals: [omega, phi, psi, sc0..3]; neighbors from smem staging ----
        if (i + 1 < n) {
            V3 Nn, CAn;
            if (tid < NT - 1) {
                const float4* nb4 = reinterpret_cast<const float4*>(fr_s + (tid + 1) * FR_STRIDE);
                float4 q0 = nb4[0], q1 = nb4[1];
                Nn  = {q0.x, q0.y, q0.z};
                CAn = {q0.w, q1.x, q1.y};
            } else {
                const float* nb = bb + (size_t)(i + 1) * 12;
                Nn  = {nb[0], nb[1], nb[2]};
                CAn = {nb[3], nb[4], nb[5]};
            }
            ang[0] = dihedral(CAv, Cv, Nn, CAn);   // omega
            ang[2] = dihedral(Nv, CAv, Cv, Nn);    // psi
        } else { ang[0] = 0.f; ang[2] = 0.f; }
        if (i > 0) {
            V3 Cp;
            if (tid > 0) {
                const float* pbs = fr_s + (tid - 1) * FR_STRIDE;
                const float4 q1 = reinterpret_cast<const float4*>(pbs)[1];
                Cp = {q1.z, q1.w, pbs[8]};
            } else {
                const float* pb = bb + (size_t)(i - 1) * 12;
                Cp = {pb[6], pb[7], pb[8]};
            }
            ang[1] = dihedral(Cp, Nv, CAv, Cv);    // phi
        } else { ang[1] = 0.f; }
        ang[3] = t4x; ang[4] = t4y; ang[5] = t4z; ang[6] = t4w;

        // ---- backbone frame ----
        V3 nrel = vsub(Nv, CAv);
        V3 crel = vsub(Cv, CAv);
        const float eps = 1e-20f;
        float txy = crel.x * crel.x + crel.y * crel.y;
        float i1 = rsqrtf(eps + txy);
        float s1 = -crel.y * i1, c1 = crel.x * i1;
        float i2 = rsqrtf(eps + txy + crel.z * crel.z);
        float s2 = crel.z * i2, c2 = sqrtf(txy) * i2;
        float Rc00 =  c2 * c1, Rc01 = -c2 * s1, Rc02 = s2;
        float Rc10 =  s1,      Rc11 =  c1;
        float Rc20 = -s2 * c1, Rc21 =  s2 * s1, Rc22 = c2;
        float n2y = Rc10 * nrel.x + Rc11 * nrel.y;
        float n2z = Rc20 * nrel.x + Rc21 * nrel.y + Rc22 * nrel.z;
        float i3 = rsqrtf(eps + n2y * n2y + n2z * n2z);
        float sn = -n2z * i3, cn = n2y * i3;
        M00 = Rc00; M01 = Rc01; M02 = Rc02;
        M10 = cn * Rc10 - sn * Rc20;
        M11 = cn * Rc11 - sn * Rc21;
        M12 = -sn * Rc22;
        M20 = sn * Rc10 + cn * Rc20;
        M21 = sn * Rc11 + cn * Rc21;
        M22 = cn * Rc22;
    }

    __syncthreads();   // neighbor bb reads done; frames may overwrite staging

    float pred[30];
    if (active) {
        const float* dfa = df_s + a_i * DF_STRIDE;
        float rr[9], rt[3];

        #pragma unroll
        for (int k = 0; k < 8; k++) {
            float d[12];
            #pragma unroll
            for (int j = 0; j < 12; j++) d[j] = dfa[k * 12 + j];
            float s, c;
            if (k == 0) { s = 0.f; c = 1.f; }
            else { __sincosf(ang[k - 1], &s, &c); }
            float f00 = d[0], f01 = c * d[1] + s * d[2],  f02 = -s * d[1] + c * d[2];
            float f10 = d[4], f11 = c * d[5] + s * d[6],  f12 = -s * d[5] + c * d[6];
            float f20 = d[8], f21 = c * d[9] + s * d[10], f22 = -s * d[9] + c * d[10];
            float ft0 = d[3], ft1 = d[7], ft2 = d[11];

            float c00, c01, c02, c10, c11, c12, c20, c21, c22, ct0, ct1, ct2;
            if (k <= 4) {
                c00 = f00; c01 = f01; c02 = f02;
                c10 = f10; c11 = f11; c12 = f12;
                c20 = f20; c21 = f21; c22 = f22;
                ct0 = ft0; ct1 = ft1; ct2 = ft2;
                if (k == 4) {
                    rr[0]=f00; rr[1]=f01; rr[2]=f02; rr[3]=f10; rr[4]=f11; rr[5]=f12;
                    rr[6]=f20; rr[7]=f21; rr[8]=f22; rt[0]=ft0; rt[1]=ft1; rt[2]=ft2;
                }
            } else {
                float n00 = rr[0]*f00 + rr[1]*f10 + rr[2]*f20;
                float n01 = rr[0]*f01 + rr[1]*f11 + rr[2]*f21;
                float n02 = rr[0]*f02 + rr[1]*f12 + rr[2]*f22;
                float n10 = rr[3]*f00 + rr[4]*f10 + rr[5]*f20;
                float n11 = rr[3]*f01 + rr[4]*f11 + rr[5]*f21;
                float n12 = rr[3]*f02 + rr[4]*f12 + rr[5]*f22;
                float n20 = rr[6]*f00 + rr[7]*f10 + rr[8]*f20;
                float n21 = rr[6]*f01 + rr[7]*f11 + rr[8]*f21;
                float n22 = rr[6]*f02 + rr[7]*f12 + rr[8]*f22;
                float nt0 = rr[0]*ft0 + rr[1]*ft1 + rr[2]*ft2 + rt[0];
                float nt1 = rr[3]*ft0 + rr[4]*ft1 + rr[5]*ft2 + rt[1];
                float nt2 = rr[6]*ft0 + rr[7]*ft1 + rr[8]*ft2 + rt[2];
                rr[0]=n00; rr[1]=n01; rr[2]=n02; rr[3]=n10; rr[4]=n11; rr[5]=n12;
                rr[6]=n20; rr[7]=n21; rr[8]=n22; rt[0]=nt0; rt[1]=nt1; rt[2]=nt2;
                c00=n00; c01=n01; c02=n02; c10=n10; c11=n11; c12=n12;
                c20=n20; c21=n21; c22=n22; ct0=nt0; ct1=nt1; ct2=nt2;
            }
            // store LOCAL composed frame (bb_r applied later, per atom)
            float4* fb = reinterpret_cast<float4*>(myfr + k * 12);
            fb[0] = make_float4(c00, c01, c02, c10);
            fb[1] = make_float4(c11, c12, c20, c21);
            fb[2] = make_float4(c22, ct0, ct1, ct2);
        }

        // ---- atoms 4..13: gather local frame, v = c@lit + ct, pred = M^T v + CA, * mask ----
        const float* ata = at_s + a_i * AT_STRIDE;
        #pragma unroll
        for (int a = 0; a < 10; a++) {
            int g    = __float_as_int(ata[a * 5 + 0]);
            float m  = ata[a * 5 + 1];
            float lx = ata[a * 5 + 2];
            float ly = ata[a * 5 + 3];
            float lz = ata[a * 5 + 4];
            const float4* fb = reinterpret_cast<const float4*>(myfr + g * 12);
            float4 A = fb[0], B = fb[1], Cq = fb[2];
            float vx = A.x * lx + A.y * ly + A.z  * lz + Cq.y;
            float vy = A.w * lx + B.x * ly + B.y  * lz + Cq.z;
            float vz = B.z * lx + B.w * ly + Cq.x * lz + Cq.w;
            pred[a * 3 + 0] = (M00 * vx + M10 * vy + M20 * vz + CAv.x) * m;
            pred[a * 3 + 1] = (M01 * vx + M11 * vy + M21 * vz + CAv.y) * m;
            pred[a * 3 + 2] = (M02 * vx + M12 * vy + M22 * vz + CAv.z) * m;
        }
    }

    // ---- staged, coalesced output: stride-42 stage + linear float4 copy ----
    __syncthreads();   // all frame reads done; reuse frame region as staging
    if (active) {
        float* st = smem + tid * 42;
        #pragma unroll
        for (int j = 0; j < 12; j++) st[j] = bbv[j];
        #pragma unroll
        for (int j = 0; j < 30; j++) st[12 + j] = pred[j];
    }
    __syncthreads();

    int nvalid = n - base; if (nvalid > NT) nvalid = NT;
    int total = nvalid * 42;
    float* gout = out + (size_t)base * 42;
    int total4 = total >> 2;
    const float4* s4 = reinterpret_cast<const float4*>(smem);
    float4* g4 = reinterpret_cast<float4*>(gout);
    for (int idx = tid; idx < total4; idx += NT) g4[idx] = s4[idx];
    for (int idx = (total4 << 2) + tid; idx < total; idx += NT) gout[idx] = smem[idx];
}

extern "C" void kernel_launch(void* const* d_in, const int* in_sizes, int n_in,
                              void* d_out, int out_size) {
    const int*   aa    = (const int*)d_in[0];
    const float* bb    = (const float*)d_in[1];
    const float* tor   = (const float*)d_in[2];
    const float* dfr   = (const float*)d_in[3];
    const int*   gidx  = (const int*)d_in[4];
    const float* amask = (const float*)d_in[5];
    const float* lit   = (const float*)d_in[6];
    float* out = (float*)d_out;

    int n = in_sizes[0];
    int grid = (n + NT - 1) / NT;
    size_t smem_bytes = (size_t)SMEM_FLOATS * sizeof(float);   // 114832 B -> 2 blocks/SM
    cudaFuncSetAttribute(idealizer_kernel, cudaFuncAttributeMaxDynamicSharedMemorySize,
                         (int)smem_bytes);
    idealizer_kernel<<<grid, NT, smem_bytes>>>(aa, bb, tor, dfr, gidx, amask, lit, out, n);
}

// round 7
// speedup vs baseline: 1.1809x; 1.1809x over previous
#include <cuda_runtime.h>
#include <math.h>

#define NT 256
#define DF_STRIDE 97          // odd -> conflict-free scalar LDS across random aa
#define AT_STRIDE 51          // odd
#define FR_FLOATS (96 * NT)   // frames [comp 0..95][tid]
#define DF_FLOATS (21 * DF_STRIDE)
#define AT_FLOATS (21 * AT_STRIDE)
#define SMEM_FLOATS (FR_FLOATS + DF_FLOATS + AT_FLOATS)   // 110.7 KB -> 2 blocks/SM

struct V3 { float x, y, z; };

__device__ __forceinline__ V3 vsub(V3 a, V3 b) { return V3{a.x - b.x, a.y - b.y, a.z - b.z}; }
__device__ __forceinline__ V3 vcross(V3 a, V3 b) {
    return V3{a.y * b.z - a.z * b.y, a.z * b.x - a.x * b.z, a.x * b.y - a.y * b.x};
}
__device__ __forceinline__ float vdot(V3 a, V3 b) { return a.x * b.x + a.y * b.y + a.z * b.z; }

// fast atan2: minimax poly on [0,1] + quadrant fixes. |err| ~1e-6 rad << 1e-3 budget.
// (0,0) -> NaN -> caught by caller's nan_to_num (reference arctan2(0,0)=0 too).
__device__ __forceinline__ float fast_atan2f(float y, float x) {
    float ax = fabsf(x), ay = fabsf(y);
    float mx = fmaxf(ax, ay), mn = fminf(ax, ay);
    float t = __fdividef(mn, mx);
    float t2 = t * t;
    float p = -0.0117212f;
    p = fmaf(p, t2,  0.05265332f);
    p = fmaf(p, t2, -0.11643287f);
    p = fmaf(p, t2,  0.19354346f);
    p = fmaf(p, t2, -0.33262347f);
    p = fmaf(p, t2,  0.99997726f);
    float r = p * t;
    r = (ay > ax) ? (1.5707963267948966f - r) : r;
    r = (x < 0.0f) ? (3.14159265358979323846f - r) : r;
    return copysignf(r, y);
}

// Matches reference _dihedral (including nan_to_num -> 0)
__device__ __forceinline__ float dihedral(V3 p0, V3 p1, V3 p2, V3 p3) {
    V3 b0 = vsub(p0, p1);
    V3 b1 = vsub(p2, p1);
    V3 b2 = vsub(p3, p2);
    V3 v1 = vcross(b0, b1);
    V3 v2 = vcross(b2, b1);
    float y = vdot(vcross(v1, v2), b1) * rsqrtf(vdot(b1, b1));
    float x = vdot(v1, v2);
    float a = fast_atan2f(y, x);
    return (a != a) ? 0.0f : a;
}

__global__ void __launch_bounds__(NT)
idealizer_kernel(const int* __restrict__ aa,
                 const float* __restrict__ bb,      // [n,4,3]
                 const float* __restrict__ tor,     // [n,4]
                 const float* __restrict__ dfr,     // [21,8,4,4]
                 const int* __restrict__ gidx,      // [21,14]
                 const float* __restrict__ amask,   // [21,14]
                 const float* __restrict__ lit,     // [21,14,3]
                 float* __restrict__ out,           // [n,14,3]
                 int n)
{
    extern __shared__ float smem[];
    float* fr_s = smem;                 // frames [comp][tid]; rows 0..11 double as bb staging; later output staging
    float* df_s = smem + FR_FLOATS;     // [21][97]
    float* at_s = df_s + DF_FLOATS;     // [21][51]

    const int tid = threadIdx.x;
    const int base = blockIdx.x * NT;
    const int i = base + tid;
    const bool active = i < n;

    float bbv[12];
    float t4x, t4y, t4z, t4w;
    int a_i = 0;

    if (active) {
        const float4* b4 = reinterpret_cast<const float4*>(bb) + (size_t)i * 3;
        float4 q0 = b4[0], q1 = b4[1], q2 = b4[2];
        bbv[0] = q0.x; bbv[1] = q0.y; bbv[2]  = q0.z; bbv[3]  = q0.w;
        bbv[4] = q1.x; bbv[5] = q1.y; bbv[6]  = q1.z; bbv[7]  = q1.w;
        bbv[8] = q2.x; bbv[9] = q2.y; bbv[10] = q2.z; bbv[11] = q2.w;
        const float4 t4 = reinterpret_cast<const float4*>(tor)[i];
        t4x = t4.x; t4y = t4.y; t4z = t4.z; t4w = t4.w;
        a_i = aa[i];
        // stage bb for neighbor dihedral reads
        #pragma unroll
        for (int c = 0; c < 12; c++) fr_s[c * NT + tid] = bbv[c];
    }

    // ---- cooperative table loads into padded smem ----
    for (int idx = tid; idx < 21 * 96; idx += NT) {
        int a = idx / 96;
        int r = idx - a * 96;                   // r = k*12 + j
        int k = r / 12;
        int j = r - k * 12;
        df_s[a * DF_STRIDE + r] = __ldg(dfr + a * 128 + k * 16 + j);
    }
    for (int idx = tid; idx < 21 * 10; idx += NT) {
        int a = idx / 10;
        int at = idx - a * 10;
        int ai = a * 14 + at + 4;
        float* dst = at_s + a * AT_STRIDE + at * 5;
        dst[0] = __int_as_float(__ldg(gidx + ai));
        dst[1] = __ldg(amask + ai);
        dst[2] = __ldg(lit + (size_t)ai * 3 + 0);
        dst[3] = __ldg(lit + (size_t)ai * 3 + 1);
        dst[4] = __ldg(lit + (size_t)ai * 3 + 2);
    }
    __syncthreads();

    float ang[7];
    float M00, M01, M02, M10, M11, M12, M20, M21, M22;
    V3 CAv;

    if (active) {
        V3 Nv  = {bbv[0], bbv[1], bbv[2]};
        CAv    = {bbv[3], bbv[4], bbv[5]};
        V3 Cv  = {bbv[6], bbv[7], bbv[8]};

        // ---- dihedrals: [omega, phi, psi, sc0..3]; neighbors from smem staging ----
        if (i + 1 < n) {
            V3 Nn, CAn;
            if (tid < NT - 1) {
                Nn  = {fr_s[0 * NT + tid + 1], fr_s[1 * NT + tid + 1], fr_s[2 * NT + tid + 1]};
                CAn = {fr_s[3 * NT + tid + 1], fr_s[4 * NT + tid + 1], fr_s[5 * NT + tid + 1]};
            } else {
                const float* nb = bb + (size_t)(i + 1) * 12;
                Nn  = {nb[0], nb[1], nb[2]};
                CAn = {nb[3], nb[4], nb[5]};
            }
            ang[0] = dihedral(CAv, Cv, Nn, CAn);   // omega
            ang[2] = dihedral(Nv, CAv, Cv, Nn);    // psi
        } else { ang[0] = 0.f; ang[2] = 0.f; }
        if (i > 0) {
            V3 Cp;
            if (tid > 0) {
                Cp = {fr_s[6 * NT + tid - 1], fr_s[7 * NT + tid - 1], fr_s[8 * NT + tid - 1]};
            } else {
                const float* pb = bb + (size_t)(i - 1) * 12;
                Cp = {pb[6], pb[7], pb[8]};
            }
            ang[1] = dihedral(Cp, Nv, CAv, Cv);    // phi
        } else { ang[1] = 0.f; }
        ang[3] = t4x; ang[4] = t4y; ang[5] = t4z; ang[6] = t4w;

        // ---- backbone frame ----
        V3 nrel = vsub(Nv, CAv);
        V3 crel = vsub(Cv, CAv);
        const float eps = 1e-20f;
        float txy = crel.x * crel.x + crel.y * crel.y;
        float i1 = rsqrtf(eps + txy);
        float s1 = -crel.y * i1, c1 = crel.x * i1;
        float i2 = rsqrtf(eps + txy + crel.z * crel.z);
        float s2 = crel.z * i2, c2 = sqrtf(txy) * i2;
        float Rc00 =  c2 * c1, Rc01 = -c2 * s1, Rc02 = s2;
        float Rc10 =  s1,      Rc11 =  c1;
        float Rc20 = -s2 * c1, Rc21 =  s2 * s1, Rc22 = c2;
        float n2y = Rc10 * nrel.x + Rc11 * nrel.y;
        float n2z = Rc20 * nrel.x + Rc21 * nrel.y + Rc22 * nrel.z;
        float i3 = rsqrtf(eps + n2y * n2y + n2z * n2z);
        float sn = -n2z * i3, cn = n2y * i3;
        M00 = Rc00; M01 = Rc01; M02 = Rc02;
        M10 = cn * Rc10 - sn * Rc20;
        M11 = cn * Rc11 - sn * Rc21;
        M12 = -sn * Rc22;
        M20 = sn * Rc10 + cn * Rc20;
        M21 = sn * Rc11 + cn * Rc21;
        M22 = cn * Rc22;
    }

    __syncthreads();   // neighbor bb reads done; frames may overwrite staging

    float pred[30];
    if (active) {
        const float* dfa = df_s + a_i * DF_STRIDE;
        float rr[9], rt[3];

        #pragma unroll
        for (int k = 0; k < 8; k++) {
            float d[12];
            #pragma unroll
            for (int j = 0; j < 12; j++) d[j] = dfa[k * 12 + j];
            float s, c;
            if (k == 0) { s = 0.f; c = 1.f; }
            else { __sincosf(ang[k - 1], &s, &c); }
            float f00 = d[0], f01 = c * d[1] + s * d[2],  f02 = -s * d[1] + c * d[2];
            float f10 = d[4], f11 = c * d[5] + s * d[6],  f12 = -s * d[5] + c * d[6];
            float f20 = d[8], f21 = c * d[9] + s * d[10], f22 = -s * d[9] + c * d[10];
            float ft0 = d[3], ft1 = d[7], ft2 = d[11];

            float c00, c01, c02, c10, c11, c12, c20, c21, c22, ct0, ct1, ct2;
            if (k <= 4) {
                c00 = f00; c01 = f01; c02 = f02;
                c10 = f10; c11 = f11; c12 = f12;
                c20 = f20; c21 = f21; c22 = f22;
                ct0 = ft0; ct1 = ft1; ct2 = ft2;
                if (k == 4) {
                    rr[0]=f00; rr[1]=f01; rr[2]=f02; rr[3]=f10; rr[4]=f11; rr[5]=f12;
                    rr[6]=f20; rr[7]=f21; rr[8]=f22; rt[0]=ft0; rt[1]=ft1; rt[2]=ft2;
                }
            } else {
                float n00 = rr[0]*f00 + rr[1]*f10 + rr[2]*f20;
                float n01 = rr[0]*f01 + rr[1]*f11 + rr[2]*f21;
                float n02 = rr[0]*f02 + rr[1]*f12 + rr[2]*f22;
                float n10 = rr[3]*f00 + rr[4]*f10 + rr[5]*f20;
                float n11 = rr[3]*f01 + rr[4]*f11 + rr[5]*f21;
                float n12 = rr[3]*f02 + rr[4]*f12 + rr[5]*f22;
                float n20 = rr[6]*f00 + rr[7]*f10 + rr[8]*f20;
                float n21 = rr[6]*f01 + rr[7]*f11 + rr[8]*f21;
                float n22 = rr[6]*f02 + rr[7]*f12 + rr[8]*f22;
                float nt0 = rr[0]*ft0 + rr[1]*ft1 + rr[2]*ft2 + rt[0];
                float nt1 = rr[3]*ft0 + rr[4]*ft1 + rr[5]*ft2 + rt[1];
                float nt2 = rr[6]*ft0 + rr[7]*ft1 + rr[8]*ft2 + rt[2];
                rr[0]=n00; rr[1]=n01; rr[2]=n02; rr[3]=n10; rr[4]=n11; rr[5]=n12;
                rr[6]=n20; rr[7]=n21; rr[8]=n22; rt[0]=nt0; rt[1]=nt1; rt[2]=nt2;
                c00=n00; c01=n01; c02=n02; c10=n10; c11=n11; c12=n12;
                c20=n20; c21=n21; c22=n22; ct0=nt0; ct1=nt1; ct2=nt2;
            }
            // store LOCAL composed frame ([comp][tid], conflict-free); bb_r applied per atom
            int kb = k * 12;
            fr_s[(kb + 0) * NT + tid] = c00;
            fr_s[(kb + 1) * NT + tid] = c01;
            fr_s[(kb + 2) * NT + tid] = c02;
            fr_s[(kb + 3) * NT + tid] = c10;
            fr_s[(kb + 4) * NT + tid] = c11;
            fr_s[(kb + 5) * NT + tid] = c12;
            fr_s[(kb + 6) * NT + tid] = c20;
            fr_s[(kb + 7) * NT + tid] = c21;
            fr_s[(kb + 8) * NT + tid] = c22;
            fr_s[(kb + 9) * NT + tid] = ct0;
            fr_s[(kb + 10) * NT + tid] = ct1;
            fr_s[(kb + 11) * NT + tid] = ct2;
        }

        // ---- atoms 4..13: gather local frame, v = c@lit + ct, pred = (M^T v + CA) * m ----
        const float* ata = at_s + a_i * AT_STRIDE;
        #pragma unroll
        for (int a = 0; a < 10; a++) {
            int g    = __float_as_int(ata[a * 5 + 0]);
            float m  = ata[a * 5 + 1];
            float lx = ata[a * 5 + 2];
            float ly = ata[a * 5 + 3];
            float lz = ata[a * 5 + 4];
            int gb = g * 12;
            // conflict-free: bank = tid mod 32 independent of g
            float c00 = fr_s[(gb + 0) * NT + tid];
            float c01 = fr_s[(gb + 1) * NT + tid];
            float c02 = fr_s[(gb + 2) * NT + tid];
            float c10 = fr_s[(gb + 3) * NT + tid];
            float c11 = fr_s[(gb + 4) * NT + tid];
            float c12 = fr_s[(gb + 5) * NT + tid];
            float c20 = fr_s[(gb + 6) * NT + tid];
            float c21 = fr_s[(gb + 7) * NT + tid];
            float c22 = fr_s[(gb + 8) * NT + tid];
            float ct0 = fr_s[(gb + 9) * NT + tid];
            float ct1 = fr_s[(gb + 10) * NT + tid];
            float ct2 = fr_s[(gb + 11) * NT + tid];
            float vx = c00 * lx + c01 * ly + c02 * lz + ct0;
            float vy = c10 * lx + c11 * ly + c12 * lz + ct1;
            float vz = c20 * lx + c21 * ly + c22 * lz + ct2;
            pred[a * 3 + 0] = (M00 * vx + M10 * vy + M20 * vz + CAv.x) * m;
            pred[a * 3 + 1] = (M01 * vx + M11 * vy + M21 * vz + CAv.y) * m;
            pred[a * 3 + 2] = (M02 * vx + M12 * vy + M22 * vz + CAv.z) * m;
        }
    }

    // ---- output: stage linear image at stride 42 (2-way STS conflict), float4 copy out ----
    __syncthreads();   // all frame reads done; reuse smem as staging
    if (active) {
        float* st = smem + tid * 42;
        #pragma unroll
        for (int j = 0; j < 12; j++) st[j] = bbv[j];
        #pragma unroll
        for (int j = 0; j < 30; j++) st[12 + j] = pred[j];
    }
    __syncthreads();

    int nvalid = n - base; if (nvalid > NT) nvalid = NT;
    int total = nvalid * 42;
    float* gout = out + (size_t)base * 42;
    int total4 = total >> 2;
    const float4* s4 = reinterpret_cast<const float4*>(smem);
    float4* g4 = reinterpret_cast<float4*>(gout);
    for (int idx = tid; idx < total4; idx += NT) g4[idx] = s4[idx];
    for (int idx = (total4 << 2) + tid; idx < total; idx += NT) gout[idx] = smem[idx];
}

extern "C" void kernel_launch(void* const* d_in, const int* in_sizes, int n_in,
                              void* d_out, int out_size) {
    const int*   aa    = (const int*)d_in[0];
    const float* bb    = (const float*)d_in[1];
    const float* tor   = (const float*)d_in[2];
    const float* dfr   = (const float*)d_in[3];
    const int*   gidx  = (const int*)d_in[4];
    const float* amask = (const float*)d_in[5];
    const float* lit   = (const float*)d_in[6];
    float* out = (float*)d_out;

    int n = in_sizes[0];
    int grid = (n + NT - 1) / NT;
    size_t smem_bytes = (size_t)SMEM_FLOATS * sizeof(float);
    cudaFuncSetAttribute(idealizer_kernel, cudaFuncAttributeMaxDynamicSharedMemorySize,
                         (int)smem_bytes);
    idealizer_kernel<<<grid, NT, smem_bytes>>>(aa, bb, tor, dfr, gidx, amask, lit, out, n);
}